// round 10
// baseline (speedup 1.0000x reference)
#include <cuda_runtime.h>
#include <cuda_bf16.h>
#include <cstdint>

#define N 8192
#define D 128
#define NPAIRS 2080
#define LDS 136                  // feature tile smem row stride (bf16)
#define FN_SCALE 4.539815982f    // sqrt(log2(e)/0.07)

// dynamic smem layout (bytes)
#define AS_OFF 0u                // A tile 128x136 bf16 (34816); reused as eT
#define BS_OFF 34816u            // B tile (34816)
#define MQ_OFF 69632u            // 4 quarter mask buffers, 34816 each
#define MQ_SZ  34816u            // per-quarter: P(32x544) + Q(32x544)
#define MQ_Q   17408u            // Q offset within a quarter buffer
#define MROW   544u              // mask smem row stride bytes (136 words)
#define SMEM_BYTES 208896

#define NTHREADS 512

__device__ __nv_bfloat16 g_fn[N * D];
__device__ float g_pos[N];
__device__ float g_neg[N];
__device__ unsigned int g_done;

__device__ __forceinline__ float ex2f(float x) {
    float y;
    asm("ex2.approx.ftz.f32 %0, %1;" : "=f"(y) : "f"(x));
    return y;
}

// mask (0/1) -> float via single IMAD: bits = m * 0x3F800000
__device__ __forceinline__ float m2f(int m) {
    return __int_as_float(m * 0x3F800000);
}

__device__ __forceinline__ void prefetch_l2(const void* p) {
    asm volatile("prefetch.global.L2 [%0];" :: "l"(p));
}

__device__ __forceinline__ void barq(int q) {
    asm volatile("bar.sync %0, 128;" :: "r"(q + 1) : "memory");
}

__device__ __forceinline__ void mma16816(float d[4], const uint32_t a[4],
                                         uint32_t b0, uint32_t b1) {
    asm volatile(
        "mma.sync.aligned.m16n8k16.row.col.f32.bf16.bf16.f32 "
        "{%0,%1,%2,%3}, {%4,%5,%6,%7}, {%8,%9}, {%0,%1,%2,%3};"
        : "+f"(d[0]), "+f"(d[1]), "+f"(d[2]), "+f"(d[3])
        : "r"(a[0]), "r"(a[1]), "r"(a[2]), "r"(a[3]), "r"(b0), "r"(b1));
}

// async copy of one 128x128 bf16 tile (row-major, D=128) into padded smem
__device__ __forceinline__ void copy_tile_async(uint32_t sbase,
                                                const __nv_bfloat16* __restrict__ src,
                                                int tid) {
#pragma unroll
    for (int k = 0; k < 4; k++) {
        int i = tid + k * NTHREADS;       // 0..2047 16B chunks
        int r = i >> 4, c = i & 15;
        uint32_t dst = sbase + (uint32_t)((r * LDS + c * 8) * 2);
        const void* s = src + (size_t)r * D + c * 8;
        asm volatile("cp.async.cg.shared.global [%0], [%1], 16;"
                     :: "r"(dst), "l"(s));
    }
}

// copy both masks' 32-row x 128-col block into this quarter's buffer (128 thr)
__device__ __forceinline__ void copy_mask_quarter(uint32_t mb,
                                                  const int* __restrict__ pm,
                                                  const int* __restrict__ nm,
                                                  int row0, int col0, int tq) {
#pragma unroll
    for (int k = 0; k < 16; k++) {
        int i = tq + k * 128;             // 0..2047 16B chunks
        const int* mp = (i & 1024) ? nm : pm;
        uint32_t moff = (i & 1024) ? MQ_Q : 0u;
        int r = (i >> 5) & 31, ch = i & 31;
        uint32_t dst = mb + moff + (uint32_t)r * MROW + (uint32_t)ch * 16;
        const void* s = mp + (size_t)(row0 + r) * N + col0 + ch * 4;
        asm volatile("cp.async.cg.shared.global [%0], [%1], 16;"
                     :: "r"(dst), "l"(s));
    }
}

// L2-prefetch both masks' 128x128 block at (rows r0, cols c0)
__device__ __forceinline__ void prefetch_mask_block(const int* __restrict__ pm,
                                                    const int* __restrict__ nm,
                                                    int r0, int c0, int tid) {
#pragma unroll
    for (int i = 0; i < 2; i++) {
        int L = tid + i * NTHREADS;       // 0..1023 lines
        const int* msk = (L & 512) ? nm : pm;
        int r = (L >> 2) & 127;
        int seg = L & 3;
        prefetch_l2(msk + (size_t)(r0 + r) * N + c0 + seg * 32);
    }
}

// ---------------------------------------------------------------------------
// Kernel 1: L2-normalize rows (exp scale folded) + zero accumulators/flag.
// ---------------------------------------------------------------------------
__global__ void normalize_kernel(const float* __restrict__ f) {
    int z = blockIdx.x * 256 + threadIdx.x;
    if (z < N) g_pos[z] = 0.f;
    else if (z < 2 * N) g_neg[z - N] = 0.f;
    if (z == 0) g_done = 0u;

    int warp = threadIdx.x >> 5, lane = threadIdx.x & 31;
    int row0 = blockIdx.x * 16 + warp * 2;
    const float4 v0 = ((const float4*)(f + (size_t)row0 * D))[lane];
    const float4 v1 = ((const float4*)(f + (size_t)(row0 + 1) * D))[lane];
    float s0 = v0.x * v0.x + v0.y * v0.y + v0.z * v0.z + v0.w * v0.w;
    float s1 = v1.x * v1.x + v1.y * v1.y + v1.z * v1.z + v1.w * v1.w;
#pragma unroll
    for (int o = 16; o > 0; o >>= 1) {
        s0 += __shfl_xor_sync(0xffffffffu, s0, o);
        s1 += __shfl_xor_sync(0xffffffffu, s1, o);
    }
    float r0 = FN_SCALE / fmaxf(sqrtf(s0), 1e-8f);
    float r1 = FN_SCALE / fmaxf(sqrtf(s1), 1e-8f);
    union { __nv_bfloat16 h[4]; uint2 u; } p0, p1;
    p0.h[0] = __float2bfloat16_rn(v0.x * r0);
    p0.h[1] = __float2bfloat16_rn(v0.y * r0);
    p0.h[2] = __float2bfloat16_rn(v0.z * r0);
    p0.h[3] = __float2bfloat16_rn(v0.w * r0);
    p1.h[0] = __float2bfloat16_rn(v1.x * r1);
    p1.h[1] = __float2bfloat16_rn(v1.y * r1);
    p1.h[2] = __float2bfloat16_rn(v1.z * r1);
    p1.h[3] = __float2bfloat16_rn(v1.w * r1);
    ((uint2*)(g_fn + (size_t)row0 * D))[lane] = p0.u;
    ((uint2*)(g_fn + (size_t)(row0 + 1) * D))[lane] = p1.u;
}

// ---------------------------------------------------------------------------
// Kernel 2: symmetric Gram tile with quarter-granularity mask pipeline.
// Quarter q = tid>>7 owns rows q*32..q*32+32 (warps 4q..4q+3, buffer q).
// Warp w: row block wr = w>>1 (16 rows), col half wc = w&1 (64 cols).
// The LAST CTA to finish also computes the final loss (fused reduction).
// ---------------------------------------------------------------------------
__global__ __launch_bounds__(NTHREADS, 1) void simloss_sym(const int* __restrict__ pm,
                                                           const int* __restrict__ nm,
                                                           float* __restrict__ out) {
    extern __shared__ __align__(16) char smem[];
    const uint32_t base = (uint32_t)__cvta_generic_to_shared(smem);
    const int tid = threadIdx.x;
    const int w = tid >> 5, l = tid & 31;
    const int wr = w >> 1, wc = w & 1;
    const int q = tid >> 7;               // quarter id 0..3
    const int tq = tid & 127;
    const uint32_t MB = base + MQ_OFF + (uint32_t)q * MQ_SZ;

    // ---- decode triangular pair index ----
    int k = blockIdx.x;
    int I = (int)((129.0f - sqrtf(16641.0f - 8.0f * (float)k)) * 0.5f);
    while ((I * (129 - I)) / 2 > k) I--;
    while (((I + 1) * (128 - I)) / 2 <= k) I++;
    const int J = I + (k - (I * (129 - I)) / 2);
    const int m0 = I * 128, j0 = J * 128;
    const bool isDiag = (I == J);

    // feature tiles (group 0) then this quarter's pass-1 masks (group 1)
    copy_tile_async(base + AS_OFF, g_fn + (size_t)m0 * D, tid);
    copy_tile_async(base + BS_OFF, g_fn + (size_t)j0 * D, tid);
    asm volatile("cp.async.commit_group;");
    copy_mask_quarter(MB, pm, nm, m0 + q * 32, j0, tq);
    asm volatile("cp.async.commit_group;");

    // warm L2 for pass-2 masks (issued after demand copies; drains under MMA)
    if (!isDiag) prefetch_mask_block(pm, nm, j0, m0, tid);

    asm volatile("cp.async.wait_group 1;");   // tiles ready; masks in flight
    __syncthreads();

    // ---- A frags ----
    uint32_t a[8][4];
    {
        int ar = wr * 16 + (l & 15);
        int ac = (l >> 4) * 8;
#pragma unroll
        for (int ks = 0; ks < 8; ks++) {
            uint32_t addr = base + AS_OFF + (uint32_t)((ar * LDS + ks * 16 + ac) * 2);
            asm volatile(
                "ldmatrix.sync.aligned.m8n8.x4.shared.b16 {%0,%1,%2,%3}, [%4];"
                : "=r"(a[ks][0]), "=r"(a[ks][1]), "=r"(a[ks][2]), "=r"(a[ks][3])
                : "r"(addr));
        }
    }
    __syncthreads();   // all frag reads of As done before eT overlays it

    // ---- MMA: 16 rows x 64 cols per warp; pass-1 masks drain underneath ----
    float acc[8][4];
#pragma unroll
    for (int i = 0; i < 8; i++) {
        acc[i][0] = 0.f; acc[i][1] = 0.f; acc[i][2] = 0.f; acc[i][3] = 0.f;
    }
    const int brow = (l >> 4) * 8 + (l & 7);
    const int bcol = ((l >> 3) & 1) * 8;
#pragma unroll
    for (int ks = 0; ks < 8; ks++) {
#pragma unroll
        for (int nf2 = 0; nf2 < 4; nf2++) {
            uint32_t addr = base + BS_OFF +
                (uint32_t)((((wc * 64 + nf2 * 16 + brow)) * LDS + ks * 16 + bcol) * 2);
            uint32_t b0, b1, b2, b3;
            asm volatile(
                "ldmatrix.sync.aligned.m8n8.x4.shared.b16 {%0,%1,%2,%3}, [%4];"
                : "=r"(b0), "=r"(b1), "=r"(b2), "=r"(b3)
                : "r"(addr));
            mma16816(acc[nf2 * 2], a[ks], b0, b1);
            mma16816(acc[nf2 * 2 + 1], a[ks], b2, b3);
        }
    }

    asm volatile("cp.async.wait_group 0;");   // this quarter's pass-1 masks landed
    barq(q);

    // ---- pass 1: rows in I (own quarter), masks (I,J) from smem; write eT ----
    char* eT = smem;                          // overlays As: [jcol][irow], 272B rows
    const int il0 = wr * 16 + (l >> 2), il1 = il0 + 8;
    const int rl0 = il0 & 31;                 // row local to quarter buffer
    const int gr0 = m0 + il0, gr1 = m0 + il1;
    float pA0 = 0.f, pA1 = 0.f, nA0 = 0.f, nA1 = 0.f;

#pragma unroll
    for (int nf = 0; nf < 8; nf++) {
        const int jcl = wc * 64 + nf * 8 + (l & 3) * 2;      // col in J block
        uint32_t mp = MB + (uint32_t)rl0 * MROW + (uint32_t)jcl * 4;
        uint32_t mq = mp + MQ_Q;
        int2 P0, Q0, P1, Q1;
        asm volatile("ld.shared.v2.b32 {%0,%1}, [%2];" : "=r"(P0.x), "=r"(P0.y) : "r"(mp));
        asm volatile("ld.shared.v2.b32 {%0,%1}, [%2];" : "=r"(Q0.x), "=r"(Q0.y) : "r"(mq));
        asm volatile("ld.shared.v2.b32 {%0,%1}, [%2];" : "=r"(P1.x), "=r"(P1.y) : "r"(mp + 8 * MROW));
        asm volatile("ld.shared.v2.b32 {%0,%1}, [%2];" : "=r"(Q1.x), "=r"(Q1.y) : "r"(mq + 8 * MROW));

        float e00 = ex2f(acc[nf][0]);
        float e01 = ex2f(acc[nf][1]);
        float e10 = ex2f(acc[nf][2]);
        float e11 = ex2f(acc[nf][3]);

        if (!isDiag) {
            *(__nv_bfloat16*)(eT + (size_t)jcl * 272 + il0 * 2) = __float2bfloat16_rn(e00);
            *(__nv_bfloat16*)(eT + (size_t)(jcl + 1) * 272 + il0 * 2) = __float2bfloat16_rn(e01);
            *(__nv_bfloat16*)(eT + (size_t)jcl * 272 + il1 * 2) = __float2bfloat16_rn(e10);
            *(__nv_bfloat16*)(eT + (size_t)(jcl + 1) * 272 + il1 * 2) = __float2bfloat16_rn(e11);
        } else {
            const int jc = j0 + jcl;
            if (gr0 == jc)     { P0.x = 0; Q0.x = 0; }
            if (gr0 == jc + 1) { P0.y = 0; Q0.y = 0; }
            if (gr1 == jc)     { P1.x = 0; Q1.x = 0; }
            if (gr1 == jc + 1) { P1.y = 0; Q1.y = 0; }
        }
        pA0 = fmaf(e00, m2f(P0.x), fmaf(e01, m2f(P0.y), pA0));
        nA0 = fmaf(e00, m2f(Q0.x), fmaf(e01, m2f(Q0.y), nA0));
        pA1 = fmaf(e10, m2f(P1.x), fmaf(e11, m2f(P1.y), pA1));
        nA1 = fmaf(e10, m2f(Q1.x), fmaf(e11, m2f(Q1.y), nA1));
    }

#pragma unroll
    for (int o = 1; o < 4; o <<= 1) {
        pA0 += __shfl_xor_sync(0xffffffffu, pA0, o);
        pA1 += __shfl_xor_sync(0xffffffffu, pA1, o);
        nA0 += __shfl_xor_sync(0xffffffffu, nA0, o);
        nA1 += __shfl_xor_sync(0xffffffffu, nA1, o);
    }
    if ((l & 3) == 0) {
        atomicAdd(&g_pos[gr0], pA0);
        atomicAdd(&g_neg[gr0], nA0);
        atomicAdd(&g_pos[gr1], pA1);
        atomicAdd(&g_neg[gr1], nA1);
    }

    barq(q);   // this quarter fully done reading its mask buffer

    // issue pass-2 mask copy NOW (streams during eT sync + other quarters' work)
    if (!isDiag) {
        copy_mask_quarter(MB, pm, nm, j0 + q * 32, m0, tq);
        asm volatile("cp.async.commit_group;");
    }

    __syncthreads();   // eT fully written by all quarters

    // ---- pass 2 (off-diag): rows in J (own quarter), masks (J,I), exp from eT ----
    if (!isDiag) {
        asm volatile("cp.async.wait_group 0;");
        barq(q);

        const int hr0 = j0 + il0, hr1 = j0 + il1;
        float p20 = 0.f, p21 = 0.f, n20 = 0.f, n21 = 0.f;
#pragma unroll
        for (int nf = 0; nf < 8; nf++) {
            const int icl = wc * 64 + nf * 8 + (l & 3) * 2;  // col in I block
            uint32_t mp = MB + (uint32_t)rl0 * MROW + (uint32_t)icl * 4;
            uint32_t mq = mp + MQ_Q;
            int2 P0, Q0, P1, Q1;
            asm volatile("ld.shared.v2.b32 {%0,%1}, [%2];" : "=r"(P0.x), "=r"(P0.y) : "r"(mp));
            asm volatile("ld.shared.v2.b32 {%0,%1}, [%2];" : "=r"(Q0.x), "=r"(Q0.y) : "r"(mq));
            asm volatile("ld.shared.v2.b32 {%0,%1}, [%2];" : "=r"(P1.x), "=r"(P1.y) : "r"(mp + 8 * MROW));
            asm volatile("ld.shared.v2.b32 {%0,%1}, [%2];" : "=r"(Q1.x), "=r"(Q1.y) : "r"(mq + 8 * MROW));

            __nv_bfloat162 ea = *(__nv_bfloat162*)(eT + (size_t)il0 * 272 + icl * 2);
            __nv_bfloat162 eb = *(__nv_bfloat162*)(eT + (size_t)il1 * 272 + icl * 2);
            float f00 = __bfloat162float(ea.x), f01 = __bfloat162float(ea.y);
            float f10 = __bfloat162float(eb.x), f11 = __bfloat162float(eb.y);
            p20 = fmaf(f00, m2f(P0.x), fmaf(f01, m2f(P0.y), p20));
            n20 = fmaf(f00, m2f(Q0.x), fmaf(f01, m2f(Q0.y), n20));
            p21 = fmaf(f10, m2f(P1.x), fmaf(f11, m2f(P1.y), p21));
            n21 = fmaf(f10, m2f(Q1.x), fmaf(f11, m2f(Q1.y), n21));
        }
#pragma unroll
        for (int o = 1; o < 4; o <<= 1) {
            p20 += __shfl_xor_sync(0xffffffffu, p20, o);
            p21 += __shfl_xor_sync(0xffffffffu, p21, o);
            n20 += __shfl_xor_sync(0xffffffffu, n20, o);
            n21 += __shfl_xor_sync(0xffffffffu, n21, o);
        }
        if ((l & 3) == 0) {
            atomicAdd(&g_pos[hr0], p20);
            atomicAdd(&g_neg[hr0], n20);
            atomicAdd(&g_pos[hr1], p21);
            atomicAdd(&g_neg[hr1], n21);
        }
    }

    // ---- fused final reduction: last CTA to finish computes the loss ----
    __syncthreads();
    __shared__ unsigned int s_rank;
    if (tid == 0) {
        __threadfence();
        s_rank = atomicAdd(&g_done, 1u);
    }
    __syncthreads();
    if (s_rank == NPAIRS - 1) {
        __threadfence();   // acquire: all CTAs' g_pos/g_neg atomics visible
        __shared__ double sred[16];
        double s = 0.0;
        for (int r = tid; r < N; r += NTHREADS) {
            float pos = g_pos[r];
            float neg = g_neg[r];
            s += (double)logf(pos / (pos + neg));
        }
#pragma unroll
        for (int o = 16; o > 0; o >>= 1) s += __shfl_xor_sync(0xffffffffu, s, o);
        if (l == 0) sred[w] = s;
        __syncthreads();
        if (w == 0) {
            s = (l < 16) ? sred[l] : 0.0;
#pragma unroll
            for (int o = 8; o > 0; o >>= 1) s += __shfl_xor_sync(0xffffffffu, s, o);
            if (l == 0) out[0] = (float)(-s / (double)N);
        }
    }
}

extern "C" void kernel_launch(void* const* d_in, const int* in_sizes, int n_in,
                              void* d_out, int out_size) {
    const float* features = (const float*)d_in[0];
    const int* pos_mask = (const int*)d_in[1];
    const int* neg_mask = (const int*)d_in[2];
    float* out = (float*)d_out;

    cudaFuncSetAttribute(simloss_sym, cudaFuncAttributeMaxDynamicSharedMemorySize,
                         SMEM_BYTES);

    normalize_kernel<<<N / 16, 256>>>(features);
    simloss_sym<<<NPAIRS, NTHREADS, SMEM_BYTES>>>(pos_mask, neg_mask, out);
}

// round 11
// speedup vs baseline: 1.3365x; 1.3365x over previous
#include <cuda_runtime.h>
#include <cuda_bf16.h>
#include <cstdint>

#define N 8192
#define D 128
#define NPAIRS 2080
#define NCTAS (2 * NPAIRS)
#define LDS 136                  // feature tile smem row stride (bf16)
#define FN_SCALE 4.539815982f    // sqrt(log2(e)/0.07)

// dynamic smem layout (bytes)
#define A_OFF  0u                // A half-tile 64x136 bf16 (17408), inside MQ0
#define MQ_SZ  36864u            // per-quarter mask buffer (q at q*MQ_SZ)
#define P1_Q   17408u            // pass-1 neg-mask offset within buffer
#define P2_Q   18432u            // pass-2 neg-mask offset within buffer
#define M1ROW  544u              // pass-1 mask row stride (128 cols + pad)
#define M2ROW  288u              // pass-2 mask row stride (64 cols + pad)
#define B_OFF  73728u            // B tile 128x136 bf16 (34816)
#define ET_OFF 73728u            // eT [J-col 128][I-row 64] 144B rows, overlays B
#define ETROW  144u
#define SMEM_BYTES 108544

#define NTHREADS 256

__device__ __nv_bfloat16 g_fn[N * D];
__device__ float g_pos[N];
__device__ float g_neg[N];

__device__ __forceinline__ float ex2f(float x) {
    float y;
    asm("ex2.approx.ftz.f32 %0, %1;" : "=f"(y) : "f"(x));
    return y;
}

// mask (0/1) -> float via single IMAD: bits = m * 0x3F800000
__device__ __forceinline__ float m2f(int m) {
    return __int_as_float(m * 0x3F800000);
}

__device__ __forceinline__ void prefetch_l2(const void* p) {
    asm volatile("prefetch.global.L2 [%0];" :: "l"(p));
}

__device__ __forceinline__ void barq(int q) {
    asm volatile("bar.sync %0, 128;" :: "r"(q + 1) : "memory");
}

__device__ __forceinline__ void mma16816(float d[4], const uint32_t a[4],
                                         uint32_t b0, uint32_t b1) {
    asm volatile(
        "mma.sync.aligned.m16n8k16.row.col.f32.bf16.bf16.f32 "
        "{%0,%1,%2,%3}, {%4,%5,%6,%7}, {%8,%9}, {%0,%1,%2,%3};"
        : "+f"(d[0]), "+f"(d[1]), "+f"(d[2]), "+f"(d[3])
        : "r"(a[0]), "r"(a[1]), "r"(a[2]), "r"(a[3]), "r"(b0), "r"(b1));
}

__device__ __forceinline__ void cp16(uint32_t dst, const void* src) {
    asm volatile("cp.async.cg.shared.global [%0], [%1], 16;" :: "r"(dst), "l"(src));
}

// decode upper-triangular pair index k -> (I, J)
__device__ __forceinline__ void decode_pair(int k, int& I, int& J) {
    I = (int)((129.0f - sqrtf(16641.0f - 8.0f * (float)k)) * 0.5f);
    while ((I * (129 - I)) / 2 > k) I--;
    while (((I + 1) * (128 - I)) / 2 <= k) I++;
    J = I + (k - (I * (129 - I)) / 2);
}

// ---------------------------------------------------------------------------
// Kernel 1: L2-normalize rows (exp scale folded) + zero accumulators.
// ---------------------------------------------------------------------------
__global__ void normalize_kernel(const float* __restrict__ f) {
    int z = blockIdx.x * 256 + threadIdx.x;
    if (z < N) g_pos[z] = 0.f;
    else if (z < 2 * N) g_neg[z - N] = 0.f;

    int warp = threadIdx.x >> 5, lane = threadIdx.x & 31;
    int row0 = blockIdx.x * 16 + warp * 2;
    const float4 v0 = ((const float4*)(f + (size_t)row0 * D))[lane];
    const float4 v1 = ((const float4*)(f + (size_t)(row0 + 1) * D))[lane];
    float s0 = v0.x * v0.x + v0.y * v0.y + v0.z * v0.z + v0.w * v0.w;
    float s1 = v1.x * v1.x + v1.y * v1.y + v1.z * v1.z + v1.w * v1.w;
#pragma unroll
    for (int o = 16; o > 0; o >>= 1) {
        s0 += __shfl_xor_sync(0xffffffffu, s0, o);
        s1 += __shfl_xor_sync(0xffffffffu, s1, o);
    }
    float r0 = FN_SCALE / fmaxf(sqrtf(s0), 1e-8f);
    float r1 = FN_SCALE / fmaxf(sqrtf(s1), 1e-8f);
    union { __nv_bfloat16 h[4]; uint2 u; } p0, p1;
    p0.h[0] = __float2bfloat16_rn(v0.x * r0);
    p0.h[1] = __float2bfloat16_rn(v0.y * r0);
    p0.h[2] = __float2bfloat16_rn(v0.z * r0);
    p0.h[3] = __float2bfloat16_rn(v0.w * r0);
    p1.h[0] = __float2bfloat16_rn(v1.x * r1);
    p1.h[1] = __float2bfloat16_rn(v1.y * r1);
    p1.h[2] = __float2bfloat16_rn(v1.z * r1);
    p1.h[3] = __float2bfloat16_rn(v1.w * r1);
    ((uint2*)(g_fn + (size_t)row0 * D))[lane] = p0.u;
    ((uint2*)(g_fn + (size_t)(row0 + 1) * D))[lane] = p1.u;
}

// ---------------------------------------------------------------------------
// Kernel 2: half-pair symmetric Gram tiles, 256 thr/CTA, 2 CTAs/SM.
// CTA = (pair, half): 64 I-rows x 128 J-cols. Pass 2 covers the transpose.
// Warp w: wr=w>>1 row block (16 rows of the 64), wc=w&1 col half (64 cols).
// Quarter q = tid>>7: pass-1 rows q*32..+32, pass-2 rows q*64..+64.
// ---------------------------------------------------------------------------
__global__ __launch_bounds__(NTHREADS, 2) void simloss_sym(const int* __restrict__ pm,
                                                           const int* __restrict__ nm) {
    extern __shared__ __align__(16) char smem[];
    const uint32_t base = (uint32_t)__cvta_generic_to_shared(smem);
    const int tid = threadIdx.x;
    const int w = tid >> 5, l = tid & 31;
    const int wr = w >> 1, wc = w & 1;
    const int q = tid >> 7;               // quarter id 0..1
    const int tq = tid & 127;
    const uint32_t MB = base + (uint32_t)q * MQ_SZ;

    // ---- decode (pair, half) ----
    int k = blockIdx.x;
    const int h2 = (k >= NPAIRS) ? 1 : 0;
    int kp = k - h2 * NPAIRS;
    int I, J;
    decode_pair(kp, I, J);
    const int m0 = I * 128, j0 = J * 128;
    const int mI = m0 + h2 * 64;          // this CTA's 64 I-rows
    const bool isDiag = (I == J);

    // ---- t0 L2 prefetch: pass-1 block (mI,j0) + pass-2 block (j0,mI) ----
#pragma unroll
    for (int i = 0; i < 2; i++) {
        int L = tid + i * 256;            // 0..511 lines (64 rows x 4 x 2 masks)
        const int* msk = (L & 256) ? nm : pm;
        int r = (L >> 2) & 63, seg = L & 3;
        prefetch_l2(msk + (size_t)(mI + r) * N + j0 + seg * 32);
    }
    if (!isDiag) {
#pragma unroll
        for (int i = 0; i < 2; i++) {
            int L = tid + i * 256;        // 0..511 lines (128 rows x 2 x 2 masks)
            const int* msk = (L & 256) ? nm : pm;
            int r = (L >> 1) & 127, seg = L & 1;
            prefetch_l2(msk + (size_t)(j0 + r) * N + mI + seg * 32);
        }
    }

    // ---- feature tiles: A half (64 rows), B full (128 rows) ----
#pragma unroll
    for (int k2 = 0; k2 < 4; k2++) {
        int i = tid + k2 * 256;           // 0..1023 chunks
        int r = i >> 4, c = i & 15;
        cp16(base + A_OFF + (uint32_t)((r * LDS + c * 8) * 2),
             g_fn + (size_t)(mI + r) * D + c * 8);
    }
#pragma unroll
    for (int k2 = 0; k2 < 8; k2++) {
        int i = tid + k2 * 256;           // 0..2047 chunks
        int r = i >> 4, c = i & 15;
        cp16(base + B_OFF + (uint32_t)((r * LDS + c * 8) * 2),
             g_fn + (size_t)(j0 + r) * D + c * 8);
    }
    asm volatile("cp.async.commit_group;");
    asm volatile("cp.async.wait_group 0;");
    __syncthreads();

    // ---- A frags (A region freed after this) ----
    uint32_t a[8][4];
    {
        int ar = wr * 16 + (l & 15);
        int ac = (l >> 4) * 8;
#pragma unroll
        for (int ks = 0; ks < 8; ks++) {
            uint32_t addr = base + A_OFF + (uint32_t)((ar * LDS + ks * 16 + ac) * 2);
            asm volatile(
                "ldmatrix.sync.aligned.m8n8.x4.shared.b16 {%0,%1,%2,%3}, [%4];"
                : "=r"(a[ks][0]), "=r"(a[ks][1]), "=r"(a[ks][2]), "=r"(a[ks][3])
                : "r"(addr));
        }
    }
    __syncthreads();   // A region now reusable as mask buffer

    // ---- pass-1 masks into quarter buffer (32 I-rows x 128 J-cols x 2) ----
#pragma unroll
    for (int k2 = 0; k2 < 16; k2++) {
        int i = tq + k2 * 128;            // 0..2047 chunks
        const int* mp = (i & 1024) ? nm : pm;
        uint32_t moff = (i & 1024) ? P1_Q : 0u;
        int r = (i >> 5) & 31, ch = i & 31;
        cp16(MB + moff + (uint32_t)r * M1ROW + (uint32_t)ch * 16,
             mp + (size_t)(mI + q * 32 + r) * N + j0 + ch * 4);
    }
    asm volatile("cp.async.commit_group;");

    // ---- MMA: 16 rows x 64 cols per warp; masks drain underneath ----
    float acc[8][4];
#pragma unroll
    for (int i = 0; i < 8; i++) {
        acc[i][0] = 0.f; acc[i][1] = 0.f; acc[i][2] = 0.f; acc[i][3] = 0.f;
    }
    const int brow = (l >> 4) * 8 + (l & 7);
    const int bcol = ((l >> 3) & 1) * 8;
#pragma unroll
    for (int ks = 0; ks < 8; ks++) {
#pragma unroll
        for (int nf2 = 0; nf2 < 4; nf2++) {
            uint32_t addr = base + B_OFF +
                (uint32_t)(((wc * 64 + nf2 * 16 + brow) * LDS + ks * 16 + bcol) * 2);
            uint32_t b0, b1, b2, b3;
            asm volatile(
                "ldmatrix.sync.aligned.m8n8.x4.shared.b16 {%0,%1,%2,%3}, [%4];"
                : "=r"(b0), "=r"(b1), "=r"(b2), "=r"(b3)
                : "r"(addr));
            mma16816(acc[nf2 * 2], a[ks], b0, b1);
            mma16816(acc[nf2 * 2 + 1], a[ks], b2, b3);
        }
    }

    asm volatile("cp.async.wait_group 0;");   // pass-1 masks landed
    __syncthreads();   // all warps done reading B before eT overlays it

    // ---- pass 1: I-rows (own quarter), masks (I,J) from smem; write eT ----
    const int il0 = wr * 16 + (l >> 2), il1 = il0 + 8;
    const int rl = il0 & 31;
    const int gr0 = mI + il0, gr1 = mI + il1;
    float pA0 = 0.f, pA1 = 0.f, nA0 = 0.f, nA1 = 0.f;

#pragma unroll
    for (int nf = 0; nf < 8; nf++) {
        const int jcl = wc * 64 + nf * 8 + (l & 3) * 2;      // col in J block
        uint32_t mp = MB + (uint32_t)rl * M1ROW + (uint32_t)jcl * 4;
        uint32_t mq = mp + P1_Q;
        int2 P0, Q0, P1, Q1;
        asm volatile("ld.shared.v2.b32 {%0,%1}, [%2];" : "=r"(P0.x), "=r"(P0.y) : "r"(mp));
        asm volatile("ld.shared.v2.b32 {%0,%1}, [%2];" : "=r"(Q0.x), "=r"(Q0.y) : "r"(mq));
        asm volatile("ld.shared.v2.b32 {%0,%1}, [%2];" : "=r"(P1.x), "=r"(P1.y) : "r"(mp + 8 * M1ROW));
        asm volatile("ld.shared.v2.b32 {%0,%1}, [%2];" : "=r"(Q1.x), "=r"(Q1.y) : "r"(mq + 8 * M1ROW));

        float e00 = ex2f(acc[nf][0]);
        float e01 = ex2f(acc[nf][1]);
        float e10 = ex2f(acc[nf][2]);
        float e11 = ex2f(acc[nf][3]);

        if (!isDiag) {
            char* eT = smem + ET_OFF;
            *(__nv_bfloat16*)(eT + (size_t)jcl * ETROW + il0 * 2) = __float2bfloat16_rn(e00);
            *(__nv_bfloat16*)(eT + (size_t)(jcl + 1) * ETROW + il0 * 2) = __float2bfloat16_rn(e01);
            *(__nv_bfloat16*)(eT + (size_t)jcl * ETROW + il1 * 2) = __float2bfloat16_rn(e10);
            *(__nv_bfloat16*)(eT + (size_t)(jcl + 1) * ETROW + il1 * 2) = __float2bfloat16_rn(e11);
        } else {
            const int jc = j0 + jcl;
            if (gr0 == jc)     { P0.x = 0; Q0.x = 0; }
            if (gr0 == jc + 1) { P0.y = 0; Q0.y = 0; }
            if (gr1 == jc)     { P1.x = 0; Q1.x = 0; }
            if (gr1 == jc + 1) { P1.y = 0; Q1.y = 0; }
        }
        pA0 = fmaf(e00, m2f(P0.x), fmaf(e01, m2f(P0.y), pA0));
        nA0 = fmaf(e00, m2f(Q0.x), fmaf(e01, m2f(Q0.y), nA0));
        pA1 = fmaf(e10, m2f(P1.x), fmaf(e11, m2f(P1.y), pA1));
        nA1 = fmaf(e10, m2f(Q1.x), fmaf(e11, m2f(Q1.y), nA1));
    }

#pragma unroll
    for (int o = 1; o < 4; o <<= 1) {
        pA0 += __shfl_xor_sync(0xffffffffu, pA0, o);
        pA1 += __shfl_xor_sync(0xffffffffu, pA1, o);
        nA0 += __shfl_xor_sync(0xffffffffu, nA0, o);
        nA1 += __shfl_xor_sync(0xffffffffu, nA1, o);
    }
    if ((l & 3) == 0) {
        atomicAdd(&g_pos[gr0], pA0);
        atomicAdd(&g_neg[gr0], nA0);
        atomicAdd(&g_pos[gr1], pA1);
        atomicAdd(&g_neg[gr1], nA1);
    }

    barq(q);   // quarter done reading its pass-1 buffer

    // ---- issue pass-2 masks (64 J-rows x 64 I-cols x 2) into own buffer ----
    if (!isDiag) {
#pragma unroll
        for (int k2 = 0; k2 < 16; k2++) {
            int i = tq + k2 * 128;        // 0..2047 chunks
            const int* mp = (i & 1024) ? nm : pm;
            uint32_t moff = (i & 1024) ? P2_Q : 0u;
            int r = (i >> 4) & 63, ch = i & 15;
            cp16(MB + moff + (uint32_t)r * M2ROW + (uint32_t)ch * 16,
                 mp + (size_t)(j0 + q * 64 + r) * N + mI + ch * 4);
        }
        asm volatile("cp.async.commit_group;");
    }

    __syncthreads();   // eT fully written

    // ---- pass 2: J-rows (warp w -> rows w*16..), I-cols 0..63, exp from eT ----
    if (!isDiag) {
        asm volatile("cp.async.wait_group 0;");
        barq(q);

        const int jl0 = w * 16 + (l >> 2), jl1 = jl0 + 8;
        const int rl2 = jl0 & 63;
        const int hr0 = j0 + jl0, hr1 = j0 + jl1;
        const char* eT = smem + ET_OFF;
        float p20 = 0.f, p21 = 0.f, n20 = 0.f, n21 = 0.f;
#pragma unroll
        for (int nf = 0; nf < 8; nf++) {
            const int icl = nf * 8 + (l & 3) * 2;            // col in I half
            uint32_t mp = MB + (uint32_t)rl2 * M2ROW + (uint32_t)icl * 4;
            uint32_t mq = mp + P2_Q;
            int2 P0, Q0, P1, Q1;
            asm volatile("ld.shared.v2.b32 {%0,%1}, [%2];" : "=r"(P0.x), "=r"(P0.y) : "r"(mp));
            asm volatile("ld.shared.v2.b32 {%0,%1}, [%2];" : "=r"(Q0.x), "=r"(Q0.y) : "r"(mq));
            asm volatile("ld.shared.v2.b32 {%0,%1}, [%2];" : "=r"(P1.x), "=r"(P1.y) : "r"(mp + 8 * M2ROW));
            asm volatile("ld.shared.v2.b32 {%0,%1}, [%2];" : "=r"(Q1.x), "=r"(Q1.y) : "r"(mq + 8 * M2ROW));

            __nv_bfloat162 ea = *(const __nv_bfloat162*)(eT + (size_t)jl0 * ETROW + icl * 2);
            __nv_bfloat162 eb = *(const __nv_bfloat162*)(eT + (size_t)jl1 * ETROW + icl * 2);
            float f00 = __bfloat162float(ea.x), f01 = __bfloat162float(ea.y);
            float f10 = __bfloat162float(eb.x), f11 = __bfloat162float(eb.y);
            p20 = fmaf(f00, m2f(P0.x), fmaf(f01, m2f(P0.y), p20));
            n20 = fmaf(f00, m2f(Q0.x), fmaf(f01, m2f(Q0.y), n20));
            p21 = fmaf(f10, m2f(P1.x), fmaf(f11, m2f(P1.y), p21));
            n21 = fmaf(f10, m2f(Q1.x), fmaf(f11, m2f(Q1.y), n21));
        }
#pragma unroll
        for (int o = 1; o < 4; o <<= 1) {
            p20 += __shfl_xor_sync(0xffffffffu, p20, o);
            p21 += __shfl_xor_sync(0xffffffffu, p21, o);
            n20 += __shfl_xor_sync(0xffffffffu, n20, o);
            n21 += __shfl_xor_sync(0xffffffffu, n21, o);
        }
        if ((l & 3) == 0) {
            atomicAdd(&g_pos[hr0], p20);
            atomicAdd(&g_neg[hr0], n20);
            atomicAdd(&g_pos[hr1], p21);
            atomicAdd(&g_neg[hr1], n21);
        }
    }
}

// ---------------------------------------------------------------------------
// Kernel 3: final loss reduction. One block.
// ---------------------------------------------------------------------------
__global__ void loss_kernel(float* __restrict__ out) {
    __shared__ double sred[32];
    double s = 0.0;
    for (int r = threadIdx.x; r < N; r += blockDim.x) {
        float pos = g_pos[r];
        float neg = g_neg[r];
        s += (double)logf(pos / (pos + neg));
    }
#pragma unroll
    for (int o = 16; o > 0; o >>= 1) s += __shfl_xor_sync(0xffffffffu, s, o);
    int warp = threadIdx.x >> 5, lane = threadIdx.x & 31;
    if (lane == 0) sred[warp] = s;
    __syncthreads();
    if (warp == 0) {
        s = (lane < (int)(blockDim.x >> 5)) ? sred[lane] : 0.0;
#pragma unroll
        for (int o = 16; o > 0; o >>= 1) s += __shfl_xor_sync(0xffffffffu, s, o);
        if (lane == 0) out[0] = (float)(-s / (double)N);
    }
}

extern "C" void kernel_launch(void* const* d_in, const int* in_sizes, int n_in,
                              void* d_out, int out_size) {
    const float* features = (const float*)d_in[0];
    const int* pos_mask = (const int*)d_in[1];
    const int* neg_mask = (const int*)d_in[2];
    float* out = (float*)d_out;

    cudaFuncSetAttribute(simloss_sym, cudaFuncAttributeMaxDynamicSharedMemorySize,
                         SMEM_BYTES);

    normalize_kernel<<<N / 16, 256>>>(features);
    simloss_sym<<<NCTAS, NTHREADS, SMEM_BYTES>>>(pos_mask, neg_mask);
    loss_kernel<<<1, 1024>>>(out);
}